// round 3
// baseline (speedup 1.0000x reference)
#include <cuda_runtime.h>
#include <cuda_bf16.h>
#include <cstdint>

#define TT 16          // time steps
#define BB 16          // batch
#define CC 256         // channels C (and Cc)
#define DD 512         // 2*C
#define HW 1024        // H*W

// Scratch (no allocation allowed)
__device__ float g_params[TT * BB * DD];   // [T,B,2C]

// ---------------------------------------------------------------------------
// Fused Stage 1+2: one block per batch b (16 blocks, 512 threads).
//  - threads 0..255 run the LIF scan for (b, cc) and keep spikes in smem
//  - then all 512 threads compute params[t,b,d] = sum_c sp[t,c]*W[d,c]+bias[d]
// Spikes never touch DRAM. W is streamed once per block (512KB, L2-shared
// across the 16 concurrent blocks).
// ---------------------------------------------------------------------------
__global__ void __launch_bounds__(512) head_kernel(
    const float* __restrict__ cond,
    const float* __restrict__ Wm,
    const float* __restrict__ bias) {
    __shared__ float s_sp[TT][CC];   // 16 KB
    int b = blockIdx.x;

    if (threadIdx.x < CC) {
        int cc = threadIdx.x;
        float v = 0.0f;
#pragma unroll
        for (int t = 0; t < TT; ++t) {
            float x = cond[(t * BB + b) * CC + cc];
            v = v + (x - v) * 0.5f;                  // charge (TAU=2)
            float s = (v >= 1.0f) ? 1.0f : 0.0f;     // fire
            s_sp[t][cc] = s;
            v = (1.0f - s) * v;                      // hard reset
        }
    }
    __syncthreads();

    int d = threadIdx.x;             // 0..511
    float bd = bias[d];
    float acc[TT];
#pragma unroll
    for (int t = 0; t < TT; ++t) acc[t] = bd;

    const float* __restrict__ wrow = Wm + (size_t)d * CC;
#pragma unroll 4
    for (int k = 0; k < CC; ++k) {
        float w = wrow[k];
#pragma unroll
        for (int t = 0; t < TT; ++t)
            acc[t] = fmaf(s_sp[t][k], w, acc[t]);
    }
#pragma unroll
    for (int t = 0; t < TT; ++t)
        g_params[(t * BB + b) * DD + d] = acc[t];
}

// ---------------------------------------------------------------------------
// Stage 3: FiLM elementwise (HBM-bound). Each 256-thread block covers EIGHT
// consecutive channels (8 x 1024 floats = 8192 floats). All eight float4
// loads issued up front -> MLP=8 per thread. gamma/beta fetched as two
// float4 pairs (c0 is 8-aligned). out = (1+gamma)*x + beta.
// ---------------------------------------------------------------------------
__global__ void __launch_bounds__(256) film_kernel(
    const float4* __restrict__ x, float4* __restrict__ out) {
    unsigned row0 = blockIdx.x * 8;          // first channel-row of block
    unsigned tb   = row0 >> 8;               // (t*B+b), same for all 8 rows
    unsigned c0   = row0 & (CC - 1);         // 8-aligned channel offset

    size_t base = (size_t)row0 * 256 + threadIdx.x;

    float4 v0 = x[base];
    float4 v1 = x[base + 256];
    float4 v2 = x[base + 512];
    float4 v3 = x[base + 768];
    float4 v4 = x[base + 1024];
    float4 v5 = x[base + 1280];
    float4 v6 = x[base + 1536];
    float4 v7 = x[base + 1792];

    const float4* __restrict__ p4 =
        (const float4*)(g_params + tb * DD + c0);
    float4 ga = p4[0];              // gamma[c0..c0+3]
    float4 gb = p4[1];              // gamma[c0+4..c0+7]
    float4 ba = p4[CC / 4];         // beta[c0..c0+3]
    float4 bb = p4[CC / 4 + 1];     // beta[c0+4..c0+7]

    float g0 = 1.0f + ga.x, g1 = 1.0f + ga.y, g2 = 1.0f + ga.z, g3 = 1.0f + ga.w;
    float g4 = 1.0f + gb.x, g5 = 1.0f + gb.y, g6 = 1.0f + gb.z, g7 = 1.0f + gb.w;

    float4 o;
    o.x = fmaf(g0, v0.x, ba.x); o.y = fmaf(g0, v0.y, ba.x);
    o.z = fmaf(g0, v0.z, ba.x); o.w = fmaf(g0, v0.w, ba.x);
    out[base] = o;
    o.x = fmaf(g1, v1.x, ba.y); o.y = fmaf(g1, v1.y, ba.y);
    o.z = fmaf(g1, v1.z, ba.y); o.w = fmaf(g1, v1.w, ba.y);
    out[base + 256] = o;
    o.x = fmaf(g2, v2.x, ba.z); o.y = fmaf(g2, v2.y, ba.z);
    o.z = fmaf(g2, v2.z, ba.z); o.w = fmaf(g2, v2.w, ba.z);
    out[base + 512] = o;
    o.x = fmaf(g3, v3.x, ba.w); o.y = fmaf(g3, v3.y, ba.w);
    o.z = fmaf(g3, v3.z, ba.w); o.w = fmaf(g3, v3.w, ba.w);
    out[base + 768] = o;
    o.x = fmaf(g4, v4.x, bb.x); o.y = fmaf(g4, v4.y, bb.x);
    o.z = fmaf(g4, v4.z, bb.x); o.w = fmaf(g4, v4.w, bb.x);
    out[base + 1024] = o;
    o.x = fmaf(g5, v5.x, bb.y); o.y = fmaf(g5, v5.y, bb.y);
    o.z = fmaf(g5, v5.z, bb.y); o.w = fmaf(g5, v5.w, bb.y);
    out[base + 1280] = o;
    o.x = fmaf(g6, v6.x, bb.z); o.y = fmaf(g6, v6.y, bb.z);
    o.z = fmaf(g6, v6.z, bb.z); o.w = fmaf(g6, v6.w, bb.z);
    out[base + 1536] = o;
    o.x = fmaf(g7, v7.x, bb.w); o.y = fmaf(g7, v7.y, bb.w);
    o.z = fmaf(g7, v7.z, bb.w); o.w = fmaf(g7, v7.w, bb.w);
    out[base + 1792] = o;
}

// ---------------------------------------------------------------------------
extern "C" void kernel_launch(void* const* d_in, const int* in_sizes, int n_in,
                              void* d_out, int out_size) {
    const float* x    = (const float*)d_in[0];   // [T,B,C,H,W]
    const float* cond = (const float*)d_in[1];   // [T,B,Cc]
    const float* Wm   = (const float*)d_in[2];   // [2C,Cc]
    const float* bias = (const float*)d_in[3];   // [2C]
    float* out = (float*)d_out;

    head_kernel<<<BB, 512>>>(cond, Wm, bias);
    film_kernel<<<TT * BB * CC / 8, 256>>>((const float4*)x, (float4*)out);
}

// round 4
// speedup vs baseline: 1.6461x; 1.6461x over previous
#include <cuda_runtime.h>
#include <cuda_bf16.h>
#include <cstdint>

#define TT 16          // time steps
#define BB 16          // batch
#define CC 256         // channels C (and Cc)
#define DD 512         // 2*C
#define HW 1024        // H*W

// Scratch (no allocation allowed)
__device__ float g_Wt[CC * DD];            // W transposed: [Cc][2C] = 512KB
__device__ float g_params[TT * BB * DD];   // [T,B,2C]

// ---------------------------------------------------------------------------
// Stage 0: transpose W [512,256] -> Wt [256,512] so GEMM lanes read
// contiguous addresses (1 wavefront per LDG instead of 32).
// ---------------------------------------------------------------------------
__global__ void __launch_bounds__(256) transpose_kernel(
    const float* __restrict__ W) {
    __shared__ float tile[32][33];
    int c = blockIdx.x * 32 + threadIdx.x;          // column of W (Cc)
    int d = blockIdx.y * 32 + threadIdx.y;          // row of W (2C)
#pragma unroll
    for (int j = 0; j < 32; j += 8)
        tile[threadIdx.y + j][threadIdx.x] = W[(size_t)(d + j) * CC + c];
    __syncthreads();
    int dc = blockIdx.y * 32 + threadIdx.x;         // d index (contig out)
    int cc = blockIdx.x * 32 + threadIdx.y;         // c index
#pragma unroll
    for (int j = 0; j < 32; j += 8)
        g_Wt[(size_t)(cc + j) * DD + dc] = tile[threadIdx.x][threadIdx.y + j];
}

// ---------------------------------------------------------------------------
// Stage 1+2 fused: grid (16 batches x 4 t-quarters), 512 threads (one per d).
// Threads 0..255 run the LIF scan (all 16 steps) and stash the 4 spikes of
// this block's t-quarter in smem. Then all 512 threads compute
// params[t,b,d] = sum_c sp[t,c]*Wt[c,d] + bias[d] with COALESCED Wt loads.
// ---------------------------------------------------------------------------
__global__ void __launch_bounds__(512) head_kernel(
    const float* __restrict__ cond, const float* __restrict__ bias) {
    __shared__ float4 s_sp4[4][CC / 4];    // spikes for 4 t's, float4 view
    int b  = blockIdx.x;
    int tq = blockIdx.y;                   // t-quarter: t = tq*4 + tl

    if (threadIdx.x < CC) {
        int cc = threadIdx.x;
        float v = 0.0f;
#pragma unroll
        for (int t = 0; t < TT; ++t) {
            float x = cond[(t * BB + b) * CC + cc];
            v = v + (x - v) * 0.5f;                  // charge (TAU=2)
            float s = (v >= 1.0f) ? 1.0f : 0.0f;     // fire
            if ((t >> 2) == tq)
                ((float*)s_sp4)[(t & 3) * CC + cc] = s;
            v = (1.0f - s) * v;                      // hard reset
        }
    }
    __syncthreads();

    int d = threadIdx.x;                   // 0..511
    float bd = bias[d];
    float acc0 = bd, acc1 = bd, acc2 = bd, acc3 = bd;

#pragma unroll 4
    for (int k4 = 0; k4 < CC / 4; ++k4) {
        int k = k4 * 4;
        float w0 = g_Wt[(k + 0) * DD + d];   // coalesced, L2-resident
        float w1 = g_Wt[(k + 1) * DD + d];
        float w2 = g_Wt[(k + 2) * DD + d];
        float w3 = g_Wt[(k + 3) * DD + d];
        float4 s0 = s_sp4[0][k4];            // broadcast LDS.128
        float4 s1 = s_sp4[1][k4];
        float4 s2 = s_sp4[2][k4];
        float4 s3 = s_sp4[3][k4];
        acc0 = fmaf(s0.x, w0, acc0); acc0 = fmaf(s0.y, w1, acc0);
        acc0 = fmaf(s0.z, w2, acc0); acc0 = fmaf(s0.w, w3, acc0);
        acc1 = fmaf(s1.x, w0, acc1); acc1 = fmaf(s1.y, w1, acc1);
        acc1 = fmaf(s1.z, w2, acc1); acc1 = fmaf(s1.w, w3, acc1);
        acc2 = fmaf(s2.x, w0, acc2); acc2 = fmaf(s2.y, w1, acc2);
        acc2 = fmaf(s2.z, w2, acc2); acc2 = fmaf(s2.w, w3, acc2);
        acc3 = fmaf(s3.x, w0, acc3); acc3 = fmaf(s3.y, w1, acc3);
        acc3 = fmaf(s3.z, w2, acc3); acc3 = fmaf(s3.w, w3, acc3);
    }
    int t0 = tq * 4;
    g_params[((t0 + 0) * BB + b) * DD + d] = acc0;
    g_params[((t0 + 1) * BB + b) * DD + d] = acc1;
    g_params[((t0 + 2) * BB + b) * DD + d] = acc2;
    g_params[((t0 + 3) * BB + b) * DD + d] = acc3;
}

// ---------------------------------------------------------------------------
// Stage 3: FiLM elementwise (unchanged from measured 77us / 6.3TB/s version).
// Each 256-thread block covers EIGHT consecutive channels; 8 float4 loads
// issued up front -> MLP=8. out = (1+gamma)*x + beta.
// ---------------------------------------------------------------------------
__global__ void __launch_bounds__(256) film_kernel(
    const float4* __restrict__ x, float4* __restrict__ out) {
    unsigned row0 = blockIdx.x * 8;
    unsigned tb   = row0 >> 8;
    unsigned c0   = row0 & (CC - 1);

    size_t base = (size_t)row0 * 256 + threadIdx.x;

    float4 v0 = x[base];
    float4 v1 = x[base + 256];
    float4 v2 = x[base + 512];
    float4 v3 = x[base + 768];
    float4 v4 = x[base + 1024];
    float4 v5 = x[base + 1280];
    float4 v6 = x[base + 1536];
    float4 v7 = x[base + 1792];

    const float4* __restrict__ p4 = (const float4*)(g_params + tb * DD + c0);
    float4 ga = p4[0];
    float4 gb = p4[1];
    float4 ba = p4[CC / 4];
    float4 bb = p4[CC / 4 + 1];

    float g0 = 1.0f + ga.x, g1 = 1.0f + ga.y, g2 = 1.0f + ga.z, g3 = 1.0f + ga.w;
    float g4 = 1.0f + gb.x, g5 = 1.0f + gb.y, g6 = 1.0f + gb.z, g7 = 1.0f + gb.w;

    float4 o;
    o.x = fmaf(g0, v0.x, ba.x); o.y = fmaf(g0, v0.y, ba.x);
    o.z = fmaf(g0, v0.z, ba.x); o.w = fmaf(g0, v0.w, ba.x);
    out[base] = o;
    o.x = fmaf(g1, v1.x, ba.y); o.y = fmaf(g1, v1.y, ba.y);
    o.z = fmaf(g1, v1.z, ba.y); o.w = fmaf(g1, v1.w, ba.y);
    out[base + 256] = o;
    o.x = fmaf(g2, v2.x, ba.z); o.y = fmaf(g2, v2.y, ba.z);
    o.z = fmaf(g2, v2.z, ba.z); o.w = fmaf(g2, v2.w, ba.z);
    out[base + 512] = o;
    o.x = fmaf(g3, v3.x, ba.w); o.y = fmaf(g3, v3.y, ba.w);
    o.z = fmaf(g3, v3.z, ba.w); o.w = fmaf(g3, v3.w, ba.w);
    out[base + 768] = o;
    o.x = fmaf(g4, v4.x, bb.x); o.y = fmaf(g4, v4.y, bb.x);
    o.z = fmaf(g4, v4.z, bb.x); o.w = fmaf(g4, v4.w, bb.x);
    out[base + 1024] = o;
    o.x = fmaf(g5, v5.x, bb.y); o.y = fmaf(g5, v5.y, bb.y);
    o.z = fmaf(g5, v5.z, bb.y); o.w = fmaf(g5, v5.w, bb.y);
    out[base + 1280] = o;
    o.x = fmaf(g6, v6.x, bb.z); o.y = fmaf(g6, v6.y, bb.z);
    o.z = fmaf(g6, v6.z, bb.z); o.w = fmaf(g6, v6.w, bb.z);
    out[base + 1536] = o;
    o.x = fmaf(g7, v7.x, bb.w); o.y = fmaf(g7, v7.y, bb.w);
    o.z = fmaf(g7, v7.z, bb.w); o.w = fmaf(g7, v7.w, bb.w);
    out[base + 1792] = o;
}

// ---------------------------------------------------------------------------
extern "C" void kernel_launch(void* const* d_in, const int* in_sizes, int n_in,
                              void* d_out, int out_size) {
    const float* x    = (const float*)d_in[0];   // [T,B,C,H,W]
    const float* cond = (const float*)d_in[1];   // [T,B,Cc]
    const float* Wm   = (const float*)d_in[2];   // [2C,Cc]
    const float* bias = (const float*)d_in[3];   // [2C]
    float* out = (float*)d_out;

    transpose_kernel<<<dim3(CC / 32, DD / 32), dim3(32, 8)>>>(Wm);
    head_kernel<<<dim3(BB, 4), 512>>>(cond, bias);
    film_kernel<<<TT * BB * CC / 8, 256>>>((const float4*)x, (float4*)out);
}

// round 5
// speedup vs baseline: 1.7922x; 1.0887x over previous
#include <cuda_runtime.h>
#include <cuda_bf16.h>
#include <cstdint>

#define TT 16          // time steps
#define BB 16          // batch
#define CC 256         // channels C (and Cc)
#define DD 512         // 2*C
#define HW 1024        // H*W

// Scratch (no allocation allowed)
__device__ float g_params[TT * BB * DD];   // [T,B,2C]

// ---------------------------------------------------------------------------
// Fused Stage 1+2 (no transpose). Grid: 256 blocks x 1024 threads.
//   block -> b = bid/16, d-base = (bid%16)*32 ; warp w handles d = dbase+w.
// Phase A: threads 0..255 run the LIF scan for (b,cc). All 16 cond loads are
//   hoisted up front (independent of v) -> one memory round-trip, then the
//   serial recurrence runs in registers. Spikes -> smem.
// Phase B: one warp per d. Lane l owns k = {l, l+32, ..., l+224}:
//   W[d, 32i+l] is a coalesced 128B LDG.32 across the warp (native layout,
//   NO transpose). s_sp[t][32i+l] is bank-conflict-free. 16 accumulators,
//   5-stage butterfly reduction, lanes 0..15 write params for t=lane.
// ---------------------------------------------------------------------------
__global__ void __launch_bounds__(1024) head_kernel(
    const float* __restrict__ cond,
    const float* __restrict__ Wm,
    const float* __restrict__ bias) {
    __shared__ float s_sp[TT][CC];   // 16 KB
    int b     = blockIdx.x >> 4;
    int dbase = (blockIdx.x & 15) * 32;

    if (threadIdx.x < CC) {
        int cc = threadIdx.x;
        float xv[TT];
#pragma unroll
        for (int t = 0; t < TT; ++t)             // independent loads, MLP=16
            xv[t] = cond[(t * BB + b) * CC + cc];
        float v = 0.0f;
#pragma unroll
        for (int t = 0; t < TT; ++t) {
            v = v + (xv[t] - v) * 0.5f;              // charge (TAU=2)
            float s = (v >= 1.0f) ? 1.0f : 0.0f;     // fire
            s_sp[t][cc] = s;
            v = (1.0f - s) * v;                      // hard reset
        }
    }
    __syncthreads();

    int w = threadIdx.x >> 5;        // warp 0..31
    int l = threadIdx.x & 31;        // lane
    int d = dbase + w;

    const float* __restrict__ wrow = Wm + (size_t)d * CC + l;

    float acc[TT];
#pragma unroll
    for (int t = 0; t < TT; ++t) acc[t] = 0.0f;

#pragma unroll
    for (int i = 0; i < CC / 32; ++i) {          // 8 iterations
        float wv = wrow[i * 32];                 // coalesced 128B across warp
#pragma unroll
        for (int t = 0; t < TT; ++t)
            acc[t] = fmaf(s_sp[t][i * 32 + l], wv, acc[t]);
    }

    // butterfly reduce all 16 accumulators across the warp
#pragma unroll
    for (int m = 16; m >= 1; m >>= 1) {
#pragma unroll
        for (int t = 0; t < TT; ++t)
            acc[t] += __shfl_xor_sync(0xFFFFFFFFu, acc[t], m);
    }

    if (l < TT)
        g_params[(l * BB + b) * DD + d] = acc[l] + bias[d];
}

// ---------------------------------------------------------------------------
// Stage 3: FiLM elementwise (unchanged: measured 77us @ 6.29TB/s).
// Each 256-thread block covers EIGHT consecutive channels; 8 float4 loads
// issued up front -> MLP=8. out = (1+gamma)*x + beta.
// ---------------------------------------------------------------------------
__global__ void __launch_bounds__(256) film_kernel(
    const float4* __restrict__ x, float4* __restrict__ out) {
    unsigned row0 = blockIdx.x * 8;
    unsigned tb   = row0 >> 8;
    unsigned c0   = row0 & (CC - 1);

    size_t base = (size_t)row0 * 256 + threadIdx.x;

    float4 v0 = x[base];
    float4 v1 = x[base + 256];
    float4 v2 = x[base + 512];
    float4 v3 = x[base + 768];
    float4 v4 = x[base + 1024];
    float4 v5 = x[base + 1280];
    float4 v6 = x[base + 1536];
    float4 v7 = x[base + 1792];

    const float4* __restrict__ p4 = (const float4*)(g_params + tb * DD + c0);
    float4 ga = p4[0];
    float4 gb = p4[1];
    float4 ba = p4[CC / 4];
    float4 bb = p4[CC / 4 + 1];

    float g0 = 1.0f + ga.x, g1 = 1.0f + ga.y, g2 = 1.0f + ga.z, g3 = 1.0f + ga.w;
    float g4 = 1.0f + gb.x, g5 = 1.0f + gb.y, g6 = 1.0f + gb.z, g7 = 1.0f + gb.w;

    float4 o;
    o.x = fmaf(g0, v0.x, ba.x); o.y = fmaf(g0, v0.y, ba.x);
    o.z = fmaf(g0, v0.z, ba.x); o.w = fmaf(g0, v0.w, ba.x);
    out[base] = o;
    o.x = fmaf(g1, v1.x, ba.y); o.y = fmaf(g1, v1.y, ba.y);
    o.z = fmaf(g1, v1.z, ba.y); o.w = fmaf(g1, v1.w, ba.y);
    out[base + 256] = o;
    o.x = fmaf(g2, v2.x, ba.z); o.y = fmaf(g2, v2.y, ba.z);
    o.z = fmaf(g2, v2.z, ba.z); o.w = fmaf(g2, v2.w, ba.z);
    out[base + 512] = o;
    o.x = fmaf(g3, v3.x, ba.w); o.y = fmaf(g3, v3.y, ba.w);
    o.z = fmaf(g3, v3.z, ba.w); o.w = fmaf(g3, v3.w, ba.w);
    out[base + 768] = o;
    o.x = fmaf(g4, v4.x, bb.x); o.y = fmaf(g4, v4.y, bb.x);
    o.z = fmaf(g4, v4.z, bb.x); o.w = fmaf(g4, v4.w, bb.x);
    out[base + 1024] = o;
    o.x = fmaf(g5, v5.x, bb.y); o.y = fmaf(g5, v5.y, bb.y);
    o.z = fmaf(g5, v5.z, bb.y); o.w = fmaf(g5, v5.w, bb.y);
    out[base + 1280] = o;
    o.x = fmaf(g6, v6.x, bb.z); o.y = fmaf(g6, v6.y, bb.z);
    o.z = fmaf(g6, v6.z, bb.z); o.w = fmaf(g6, v6.w, bb.z);
    out[base + 1536] = o;
    o.x = fmaf(g7, v7.x, bb.w); o.y = fmaf(g7, v7.y, bb.w);
    o.z = fmaf(g7, v7.z, bb.w); o.w = fmaf(g7, v7.w, bb.w);
    out[base + 1792] = o;
}

// ---------------------------------------------------------------------------
extern "C" void kernel_launch(void* const* d_in, const int* in_sizes, int n_in,
                              void* d_out, int out_size) {
    const float* x    = (const float*)d_in[0];   // [T,B,C,H,W]
    const float* cond = (const float*)d_in[1];   // [T,B,Cc]
    const float* Wm   = (const float*)d_in[2];   // [2C,Cc]
    const float* bias = (const float*)d_in[3];   // [2C]
    float* out = (float*)d_out;

    head_kernel<<<BB * 16, 1024>>>(cond, Wm, bias);
    film_kernel<<<TT * BB * CC / 8, 256>>>((const float4*)x, (float4*)out);
}